// round 2
// baseline (speedup 1.0000x reference)
#include <cuda_runtime.h>
#include <cstdint>

#define TILE_B   16
#define TILE_N   256
#define KC       32
#define NTHREADS 256
#define GRAPHK   50
#define DFEAT    256

// Shared memory layout (floats):
//   Fs    [256][16]      features, k-major               4096
//   As    [2][32][256]   anchor chunk, k-major, swizzled 16384
//   stage [16][256]      sim chunk staging               4096
//   vals  [16][52]       top-k values                    832
//   labs  [16][52]       top-k anchor labels (int)       832
#define SM_FS    0
#define SM_AS    4096
#define SM_STAGE (4096 + 16384)
#define SM_VALS  (4096 + 16384 + 4096)
#define SM_LABS  (4096 + 16384 + 4096 + 16*52)
#define SM_FLOATS (4096 + 16384 + 4096 + 16*52 + 16*52)
#define SMEM_BYTES (SM_FLOATS * 4)

#define NEG_INF (-3.402823466e38f)
#define POS_INF ( 3.402823466e38f)
#define FULLMASK 0xffffffffu

__global__ __launch_bounds__(NTHREADS, 1)
void knn_sim_kernel(const float* __restrict__ features,
                    const float* __restrict__ anchor,
                    const int*   __restrict__ labels,
                    const int*   __restrict__ anchor_label,
                    float*       __restrict__ out,
                    int B, int N)
{
    extern __shared__ float sm[];
    float* Fs    = sm + SM_FS;
    float* As    = sm + SM_AS;
    float* stage = sm + SM_STAGE;
    float* vals  = sm + SM_VALS;
    int*   labs  = (int*)(sm + SM_LABS);

    const int tx   = threadIdx.x;
    const int tc   = tx & 63;   // 0..63 col-group
    const int tr   = tx >> 6;   // 0..3  row-group
    const int lane = tx & 31;
    const int warp = tx >> 5;   // 0..7
    const int b0   = blockIdx.x * TILE_B;

    // ---- load features tile transposed: Fs[k][r] ----
    for (int idx = tx; idx < TILE_B * DFEAT; idx += NTHREADS) {
        int r = idx >> 8;       // 0..15
        int k = idx & 255;      // 0..255
        Fs[k * TILE_B + r] = features[(size_t)(b0 + r) * DFEAT + k];
    }

    // ---- init top-k lists (each warp owns rows 2w, 2w+1) ----
    #pragma unroll
    for (int rr = 0; rr < 2; rr++) {
        int r = 2 * warp + rr;
        if (lane < GRAPHK)        { vals[r*52 + lane]      = NEG_INF; labs[r*52 + lane]      = -1; }
        if (lane + 32 < GRAPHK)   { vals[r*52 + lane + 32] = NEG_INF; labs[r*52 + lane + 32] = -1; }
    }
    float minv[2]; int minpos[2];
    minv[0] = NEG_INF; minv[1] = NEG_INF;
    minpos[0] = 0;     minpos[1] = 0;
    __syncthreads();

    const int NCHUNK = (N + TILE_N - 1) / TILE_N;
    const int k4 = tx & 7;        // 0..7  k4 group for loads
    const int nb = tx >> 3;       // 0..31 anchor base for loads
    const int swz = 4 * k4;       // XOR swizzle constant for this thread's STS

    float4 reg[8];
    // prologue: load (chunk 0, kc 0)
    #pragma unroll
    for (int q = 0; q < 8; q++) {
        int n = nb + 32 * q;
        reg[q] = (n < N) ? *(const float4*)(anchor + (size_t)n * DFEAT + 4 * k4)
                         : make_float4(0.f, 0.f, 0.f, 0.f);
    }

    for (int c = 0; c < NCHUNK; c++) {
        const int n0 = c * TILE_N;

        // ---- store regs -> As[0] (transposed, swizzled: col' = n ^ (k&28)) ----
        {
            float* p = As + (4 * k4) * TILE_N;
            #pragma unroll
            for (int q = 0; q < 8; q++) {
                int n = nb + 32 * q;
                int cidx = n ^ swz;
                p[0 * TILE_N + cidx] = reg[q].x;
                p[1 * TILE_N + cidx] = reg[q].y;
                p[2 * TILE_N + cidx] = reg[q].z;
                p[3 * TILE_N + cidx] = reg[q].w;
            }
        }
        __syncthreads();

        float acc[4][4];
        #pragma unroll
        for (int i = 0; i < 4; i++)
            #pragma unroll
            for (int j = 0; j < 4; j++) acc[i][j] = 0.f;

        int cur = 0;
        #pragma unroll 1
        for (int kci = 0; kci < 8; kci++) {
            // ---- prefetch next k-chunk (or next n-chunk's first k-chunk) ----
            if (kci < 7) {
                const int kbase = (kci + 1) * KC;
                #pragma unroll
                for (int q = 0; q < 8; q++) {
                    int n = n0 + nb + 32 * q;
                    reg[q] = (n < N) ? *(const float4*)(anchor + (size_t)n * DFEAT + kbase + 4 * k4)
                                     : make_float4(0.f, 0.f, 0.f, 0.f);
                }
            } else if (c + 1 < NCHUNK) {
                const int nn0 = (c + 1) * TILE_N;
                #pragma unroll
                for (int q = 0; q < 8; q++) {
                    int n = nn0 + nb + 32 * q;
                    reg[q] = (n < N) ? *(const float4*)(anchor + (size_t)n * DFEAT + 4 * k4)
                                     : make_float4(0.f, 0.f, 0.f, 0.f);
                }
            }

            // ---- compute: 32 k-steps, thread tile 4x4 ----
            const float* Ac  = As + cur * (KC * TILE_N);
            const int    kk0 = kci * KC;
            #pragma unroll
            for (int k = 0; k < KC; k++) {
                float4 f = *(const float4*)(Fs + (kk0 + k) * TILE_B + 4 * tr);
                float4 a = *(const float4*)(Ac + k * TILE_N + ((4 * tc) ^ (4 * (k >> 2))));
                acc[0][0] += f.x * a.x; acc[0][1] += f.x * a.y; acc[0][2] += f.x * a.z; acc[0][3] += f.x * a.w;
                acc[1][0] += f.y * a.x; acc[1][1] += f.y * a.y; acc[1][2] += f.y * a.z; acc[1][3] += f.y * a.w;
                acc[2][0] += f.z * a.x; acc[2][1] += f.z * a.y; acc[2][2] += f.z * a.z; acc[2][3] += f.z * a.w;
                acc[3][0] += f.w * a.x; acc[3][1] += f.w * a.y; acc[3][2] += f.w * a.z; acc[3][3] += f.w * a.w;
            }

            // ---- store prefetched regs into the other buffer ----
            if (kci < 7) {
                float* Aw = As + (cur ^ 1) * (KC * TILE_N) + (4 * k4) * TILE_N;
                #pragma unroll
                for (int q = 0; q < 8; q++) {
                    int n = nb + 32 * q;
                    int cidx = n ^ swz;
                    Aw[0 * TILE_N + cidx] = reg[q].x;
                    Aw[1 * TILE_N + cidx] = reg[q].y;
                    Aw[2 * TILE_N + cidx] = reg[q].z;
                    Aw[3 * TILE_N + cidx] = reg[q].w;
                }
                __syncthreads();
                cur ^= 1;
            }
        }
        __syncthreads();

        // ---- stage sims to smem ----
        #pragma unroll
        for (int i = 0; i < 4; i++) {
            *(float4*)(stage + (4 * tr + i) * TILE_N + 4 * tc) =
                make_float4(acc[i][0], acc[i][1], acc[i][2], acc[i][3]);
        }
        __syncthreads();

        // ---- top-k update: warp w scans rows 2w, 2w+1 ----
        int valid = N - n0; if (valid > TILE_N) valid = TILE_N;
        #pragma unroll
        for (int rr = 0; rr < 2; rr++) {
            const int r = 2 * warp + rr;
            const float* srow = stage + r * TILE_N;
            float mv = minv[rr]; int mp = minpos[rr];
            for (int base = 0; base < TILE_N; base += 32) {
                int j = base + lane;
                float v = srow[j];
                bool cand = (j < valid) && (v > mv);
                unsigned m = __ballot_sync(FULLMASK, cand);
                while (m) {
                    int src = __ffs(m) - 1; m &= m - 1;
                    float vv = __shfl_sync(FULLMASK, v, src);
                    if (vv > mv) {
                        if (lane == 0) {
                            vals[r*52 + mp] = vv;
                            labs[r*52 + mp] = anchor_label[n0 + base + src];
                        }
                        __syncwarp();
                        // recompute running min + argmin over 50 slots
                        float x = (lane < GRAPHK) ? vals[r*52 + lane] : POS_INF;
                        int   p = lane;
                        if (lane + 32 < GRAPHK) {
                            float x2 = vals[r*52 + lane + 32];
                            if (x2 < x) { x = x2; p = lane + 32; }
                        }
                        #pragma unroll
                        for (int off = 16; off; off >>= 1) {
                            float ox = __shfl_down_sync(FULLMASK, x, off);
                            int   op = __shfl_down_sync(FULLMASK, p, off);
                            if (ox < x) { x = ox; p = op; }
                        }
                        mv = __shfl_sync(FULLMASK, x, 0);
                        mp = __shfl_sync(FULLMASK, p, 0);
                    }
                }
            }
            minv[rr] = mv; minpos[rr] = mp;
        }
        __syncthreads();
    }

    // ---- finalize: sum top-k values, count label matches ----
    #pragma unroll
    for (int rr = 0; rr < 2; rr++) {
        const int r   = 2 * warp + rr;
        const int row = b0 + r;
        const int lbl = labels[row];
        float sv = 0.f; int cnt = 0;
        if (lane < GRAPHK)      { sv  = vals[r*52 + lane];      cnt  = (labs[r*52 + lane]      == lbl); }
        if (lane + 32 < GRAPHK) { sv += vals[r*52 + lane + 32]; cnt += (labs[r*52 + lane + 32] == lbl); }
        #pragma unroll
        for (int off = 16; off; off >>= 1) {
            sv  += __shfl_down_sync(FULLMASK, sv, off);
            cnt += __shfl_down_sync(FULLMASK, cnt, off);
        }
        if (lane == 0) {
            out[row]     = -(float)cnt * (1.0f / GRAPHK);   // loss = -mean_log_prob_pos
            out[B + row] = sv * (1.0f / GRAPHK);            // mean_sim
        }
    }
}

extern "C" void kernel_launch(void* const* d_in, const int* in_sizes, int n_in,
                              void* d_out, int out_size)
{
    const float* features     = (const float*)d_in[0];
    const float* anchor       = (const float*)d_in[1];
    const int*   labels       = (const int*)d_in[2];
    // d_in[3] = t_labels (unused by reference)
    const int*   anchor_label = (const int*)d_in[4];
    float* out = (float*)d_out;

    const int B = in_sizes[2];            // 2048
    const int N = in_sizes[4];            // 50000

    cudaFuncSetAttribute(knn_sim_kernel,
                         cudaFuncAttributeMaxDynamicSharedMemorySize, SMEM_BYTES);

    dim3 grid(B / TILE_B);                // 128 CTAs
    dim3 block(NTHREADS);
    knn_sim_kernel<<<grid, block, SMEM_BYTES>>>(features, anchor, labels,
                                                anchor_label, out, B, N);
}